// round 13
// baseline (speedup 1.0000x reference)
#include <cuda_runtime.h>
#include <cuda_bf16.h>
#include <cstdint>
#include <math.h>

#define BB 64
#define SS 64
#define FF 4096
#define HH 1024
#define CC 31
#define MM (BB*SS)

__device__ float g_xtz [MM*HH];
__device__ float g_xth1[MM*HH];
__device__ float g_x0r [BB*HH];
__device__ float g_x0z [BB*HH];
__device__ int   g_bar = 0;
__device__ int   g_ack = 0;

__device__ __align__(16) __nv_bfloat16 g_x_h  [MM*FF];
__device__ __align__(16) __nv_bfloat16 g_x_l  [MM*FF];
__device__ __align__(16) __nv_bfloat16 g_wxe_h[HH*FF];
__device__ __align__(16) __nv_bfloat16 g_wxe_l[HH*FF];
__device__ __align__(16) __nv_bfloat16 g_e_h  [MM*HH];
__device__ __align__(16) __nv_bfloat16 g_e_l  [MM*HH];
__device__ __align__(16) __nv_bfloat16 g_wz_h [HH*HH];
__device__ __align__(16) __nv_bfloat16 g_wz_l [HH*HH];
__device__ __align__(16) __nv_bfloat16 g_wh_h [HH*HH];
__device__ __align__(16) __nv_bfloat16 g_wh_l [HH*HH];
__device__ __align__(16) __nv_bfloat16 g_wr_h [HH*HH];
__device__ __align__(16) __nv_bfloat16 g_wr_l [HH*HH];
__device__ __align__(16) __nv_bfloat16 g_w1_h [HH*HH];
__device__ __align__(16) __nv_bfloat16 g_w1_l [HH*HH];
__device__ __align__(16) __nv_bfloat16 g_hs_h [2*BB*HH];
__device__ __align__(16) __nv_bfloat16 g_hs_l [2*BB*HH];

__device__ __forceinline__ uint32_t smem_u32(const void* p) {
    uint32_t a;
    asm("{ .reg .u64 t; cvta.to.shared.u64 t, %1; cvt.u32.u64 %0, t; }"
        : "=r"(a) : "l"(p));
    return a;
}
__device__ __forceinline__ void ldsm_x4(uint32_t* r, uint32_t addr) {
    asm volatile("ldmatrix.sync.aligned.m8n8.x4.shared.b16 {%0,%1,%2,%3}, [%4];"
        : "=r"(r[0]), "=r"(r[1]), "=r"(r[2]), "=r"(r[3]) : "r"(addr));
}
__device__ __forceinline__ void mma16816(float* d, const uint32_t* a, uint32_t b0, uint32_t b1) {
    asm volatile(
        "mma.sync.aligned.m16n8k16.row.col.f32.bf16.bf16.f32 "
        "{%0,%1,%2,%3}, {%4,%5,%6,%7}, {%8,%9}, {%0,%1,%2,%3};"
        : "+f"(d[0]), "+f"(d[1]), "+f"(d[2]), "+f"(d[3])
        : "r"(a[0]), "r"(a[1]), "r"(a[2]), "r"(a[3]), "r"(b0), "r"(b1));
}
__device__ __forceinline__ void cpa16(uint32_t dst, const void* src) {
    asm volatile("cp.async.ca.shared.global [%0], [%1], 16;" :: "r"(dst), "l"(src));
}
#define CP_COMMIT() asm volatile("cp.async.commit_group;")
#define CP_WAIT(N)  asm volatile("cp.async.wait_group %0;" :: "n"(N))

__device__ __forceinline__ void split2(float a, float b, uint32_t& hi, uint32_t& lo) {
    __nv_bfloat16 ha = __float2bfloat16(a);
    __nv_bfloat16 hb = __float2bfloat16(b);
    __nv_bfloat16 la = __float2bfloat16(a - __bfloat162float(ha));
    __nv_bfloat16 lb = __float2bfloat16(b - __bfloat162float(hb));
    unsigned short uha = *(unsigned short*)&ha, uhb = *(unsigned short*)&hb;
    unsigned short ula = *(unsigned short*)&la, ulb = *(unsigned short*)&lb;
    hi = (uint32_t)uha | ((uint32_t)uhb << 16);
    lo = (uint32_t)ula | ((uint32_t)ulb << 16);
}

// ======================= pack =======================
__global__ __launch_bounds__(256) void pack_rm(
    const float* __restrict__ src,
    __nv_bfloat16* __restrict__ dh, __nv_bfloat16* __restrict__ dl, int n)
{
    int i = (blockIdx.x * 256 + threadIdx.x) * 4;
    if (i < n) {
        float4 v = *(const float4*)(src + i);
        uint32_t h0, l0, h1, l1;
        split2(v.x, v.y, h0, l0);
        split2(v.z, v.w, h1, l1);
        *(uint2*)(dh + i) = make_uint2(h0, h1);
        *(uint2*)(dl + i) = make_uint2(l0, l1);
    }
}

__global__ __launch_bounds__(256) void pack_tr(
    const float* __restrict__ src,
    __nv_bfloat16* __restrict__ dh, __nv_bfloat16* __restrict__ dl,
    int Kd, int Nd)
{
    __shared__ float t[32][33];
    int n0 = blockIdx.x * 32, k0 = blockIdx.y * 32;
    int tx = threadIdx.x & 31, ty = threadIdx.x >> 5;
#pragma unroll
    for (int r = 0; r < 4; r++)
        t[ty + r*8][tx] = src[(size_t)(k0 + ty + r*8) * Nd + n0 + tx];
    __syncthreads();
#pragma unroll
    for (int r = 0; r < 4; r++) {
        int nr = ty + r * 8;
        float v = t[tx][nr];
        __nv_bfloat16 hb = __float2bfloat16(v);
        __nv_bfloat16 lb = __float2bfloat16(v - __bfloat162float(hb));
        size_t o = (size_t)(n0 + nr) * Kd + k0 + tx;
        dh[o] = hb;
        dl[o] = lb;
    }
}

__global__ __launch_bounds__(256) void pack_h0(
    const float* __restrict__ h0,
    __nv_bfloat16* __restrict__ dh, __nv_bfloat16* __restrict__ dl)
{
    int i = (blockIdx.x * 256 + threadIdx.x) * 4;
    if (i < BB * HH) {
        float4 v = *(const float4*)(h0 + i);
        uint32_t hx0, lx0, hx1, lx1;
        split2(v.x, v.y, hx0, lx0);
        split2(v.z, v.w, hx1, lx1);
        *(uint2*)(dh + i) = make_uint2(hx0, hx1);
        *(uint2*)(dl + i) = make_uint2(lx0, lx1);
    }
}

// ======================= hmma_gemm (validated) =======================
#define ASTR 40
#define MAT_B (128*ASTR*2)
#define STG_B (4*MAT_B)
__global__ __launch_bounds__(256, 2) void hmma_gemm(
    const __nv_bfloat16* __restrict__ Ah, const __nv_bfloat16* __restrict__ Al,
    const __nv_bfloat16* __restrict__ Bh, const __nv_bfloat16* __restrict__ Bl,
    const float* __restrict__ bias, float* __restrict__ C,
    int M, int N, int K, int relu,
    __nv_bfloat16* __restrict__ Ch, __nv_bfloat16* __restrict__ Cl,
    float* __restrict__ x0es)
{
    extern __shared__ __align__(16) char sm[];
    const uint32_t sbase = smem_u32(sm);
    const int tid = threadIdx.x, wid = tid >> 5, lane = tid & 31;
    const int warp_m = wid & 1, warp_n = wid >> 1;
    const int m0 = blockIdx.y * 128, n0 = blockIdx.x * 128;
    const int lrow = lane & 15, lhalf = lane >> 4;

    const int crow = tid >> 1, cseg = tid & 1;
    const __nv_bfloat16* gAh = Ah + (size_t)(m0 + crow) * K + cseg * 16;
    const __nv_bfloat16* gAl = Al + (size_t)(m0 + crow) * K + cseg * 16;
    const __nv_bfloat16* gBh = Bh + (size_t)(n0 + crow) * K + cseg * 16;
    const __nv_bfloat16* gBl = Bl + (size_t)(n0 + crow) * K + cseg * 16;
    const uint32_t dbase = sbase + (uint32_t)(crow * ASTR + cseg * 16) * 2;

    uint32_t offA[4], offB[2];
#pragma unroll
    for (int mt = 0; mt < 4; mt++)
        offA[mt] = sbase + (uint32_t)((warp_m * 64 + mt * 16 + lrow) * ASTR + lhalf * 8) * 2;
#pragma unroll
    for (int np = 0; np < 2; np++)
        offB[np] = sbase + 2 * MAT_B
                 + (uint32_t)((warp_n * 32 + np * 16 + lrow) * ASTR + lhalf * 8) * 2;

    float acc[4][4][4];
#pragma unroll
    for (int i = 0; i < 4; i++)
#pragma unroll
        for (int j = 0; j < 4; j++)
#pragma unroll
            for (int e = 0; e < 4; e++) acc[i][j][e] = 0.f;

    const int nk = K >> 5;
    {
        uint32_t d = dbase;
        cpa16(d,           gAh); cpa16(d + 16,           gAh + 8);
        cpa16(d + MAT_B,   gAl); cpa16(d + MAT_B + 16,   gAl + 8);
        cpa16(d + 2*MAT_B, gBh); cpa16(d + 2*MAT_B + 16, gBh + 8);
        cpa16(d + 3*MAT_B, gBl); cpa16(d + 3*MAT_B + 16, gBl + 8);
        CP_COMMIT();
    }
    for (int kc = 0; kc < nk; kc++) {
        if (kc + 1 < nk) {
            uint32_t d = dbase + ((kc + 1) & 1) * STG_B;
            const int go = (kc + 1) * 32;
            cpa16(d,           gAh + go); cpa16(d + 16,           gAh + go + 8);
            cpa16(d + MAT_B,   gAl + go); cpa16(d + MAT_B + 16,   gAl + go + 8);
            cpa16(d + 2*MAT_B, gBh + go); cpa16(d + 2*MAT_B + 16, gBh + go + 8);
            cpa16(d + 3*MAT_B, gBl + go); cpa16(d + 3*MAT_B + 16, gBl + go + 8);
            CP_COMMIT();
            CP_WAIT(1);
        } else {
            CP_WAIT(0);
        }
        __syncthreads();
        const uint32_t stb = (kc & 1) * STG_B;
#pragma unroll
        for (int ks = 0; ks < 2; ks++) {
            const uint32_t ko = stb + ks * 32;
            uint32_t fah[4][4], fal[4][4], fbh[2][4], fbl[2][4];
#pragma unroll
            for (int mt = 0; mt < 4; mt++) {
                ldsm_x4(fah[mt], offA[mt] + ko);
                ldsm_x4(fal[mt], offA[mt] + ko + MAT_B);
            }
#pragma unroll
            for (int np = 0; np < 2; np++) {
                ldsm_x4(fbh[np], offB[np] + ko);
                ldsm_x4(fbl[np], offB[np] + ko + MAT_B);
            }
#pragma unroll
            for (int mt = 0; mt < 4; mt++) {
#pragma unroll
                for (int ni = 0; ni < 4; ni++) {
                    const int np = ni >> 1, sub = ni & 1;
                    mma16816(acc[mt][ni], fah[mt], fbh[np][sub], fbh[np][2 + sub]);
                    mma16816(acc[mt][ni], fah[mt], fbl[np][sub], fbl[np][2 + sub]);
                    mma16816(acc[mt][ni], fal[mt], fbh[np][sub], fbh[np][2 + sub]);
                }
            }
        }
        __syncthreads();
    }
#pragma unroll
    for (int mt = 0; mt < 4; mt++) {
#pragma unroll
        for (int ni = 0; ni < 4; ni++) {
            int row = m0 + warp_m * 64 + mt * 16 + (lane >> 2);
            int col = n0 + warp_n * 32 + ni * 8 + (lane & 3) * 2;
            float b0 = __ldg(&bias[col]), b1 = __ldg(&bias[col + 1]);
            float v0 = acc[mt][ni][0] + b0;
            float v1 = acc[mt][ni][1] + b1;
            float v2 = acc[mt][ni][2] + b0;
            float v3 = acc[mt][ni][3] + b1;
            if (relu) {
                v0 = fmaxf(v0, 0.f); v1 = fmaxf(v1, 0.f);
                v2 = fmaxf(v2, 0.f); v3 = fmaxf(v3, 0.f);
            }
            *(float2*)(C + (size_t)row * N + col)       = make_float2(v0, v1);
            *(float2*)(C + (size_t)(row + 8) * N + col) = make_float2(v2, v3);
            if (Ch) {
                uint32_t h0, l0, h1, l1;
                split2(v0, v1, h0, l0);
                split2(v2, v3, h1, l1);
                *(uint32_t*)(Ch + (size_t)row * N + col)       = h0;
                *(uint32_t*)(Cl + (size_t)row * N + col)       = l0;
                *(uint32_t*)(Ch + (size_t)(row + 8) * N + col) = h1;
                *(uint32_t*)(Cl + (size_t)(row + 8) * N + col) = l1;
            }
            if (x0es && (((row + 8) & 63) == 63)) {
                int base = ((row + 8) >> 6) << 6;
#pragma unroll 4
                for (int s = 0; s < SS; s++)
                    *(float2*)(x0es + (size_t)(base + s) * N + col) = make_float2(v2, v3);
            }
        }
    }
}

// ======================= ptes / bcast / dual64 =======================
__global__ __launch_bounds__(256) void ptes_kernel(
    const float* __restrict__ xtes, const float* __restrict__ Wep,
    const float* __restrict__ bep, float* __restrict__ ptes)
{
    __shared__ float Weps[256][32];
    __shared__ float xs[8][256];
    int tid  = threadIdx.x;
    int row0 = blockIdx.x * 8;
    int warp = tid >> 5, lane = tid & 31;
    float acc = 0.f;
    for (int kb = 0; kb < HH; kb += 256) {
        for (int i = tid; i < 256 * CC; i += 256) {
            int kk = i / CC, c = i % CC;
            Weps[kk][c] = Wep[(size_t)(kb + kk) * CC + c];
        }
        for (int i = tid; i < 8 * 256; i += 256) {
            int r = i >> 8, kk = i & 255;
            xs[r][kk] = xtes[(size_t)(row0 + r) * HH + kb + kk];
        }
        __syncthreads();
        if (lane < CC) {
#pragma unroll 8
            for (int kk = 0; kk < 256; kk++)
                acc = fmaf(xs[warp][kk], Weps[kk][lane], acc);
        }
        __syncthreads();
    }
    if (lane < CC)
        ptes[(size_t)(row0 + warp) * CC + lane] = acc + bep[lane];
}

__global__ void bcast_p0es(const float* __restrict__ ptes, float* __restrict__ p0es)
{
    int idx = blockIdx.x * blockDim.x + threadIdx.x;
    if (idx < BB * SS * CC) {
        int c  = idx % CC;
        int b  = (idx / CC) / SS;
        p0es[idx] = ptes[(size_t)(b * SS + (SS - 1)) * CC + c];
    }
}

__global__ __launch_bounds__(256) void dual64_kernel(
    const float* __restrict__ A, int lda,
    const float* __restrict__ W0, const float* __restrict__ W1,
    const float* __restrict__ b0v, const float* __restrict__ b1v,
    float* __restrict__ out0, float* __restrict__ out1)
{
    __shared__ float Hs[64][65];
    __shared__ float W0s[64][16];
    __shared__ float W1s[64][16];
    int tid = threadIdx.x;
    int n0  = blockIdx.x * 16;
    int col = tid & 15;
    int rowbase = (tid >> 4) * 4;
    float a0[4] = {0,0,0,0}, a1[4] = {0,0,0,0};
    for (int kb = 0; kb < HH; kb += 64) {
#pragma unroll
        for (int i = 0; i < 4; i++) {
            int lin = tid + i * 256;
            int m = lin >> 4, kq = lin & 15;
            float4 v = *(const float4*)(A + (size_t)m * lda + kb + kq * 4);
            Hs[kq*4+0][m] = v.x; Hs[kq*4+1][m] = v.y;
            Hs[kq*4+2][m] = v.z; Hs[kq*4+3][m] = v.w;
        }
#pragma unroll
        for (int i = 0; i < 4; i++) {
            int lin = tid + i * 256;
            int kk = lin >> 4, c = lin & 15;
            W0s[kk][c] = W0[(size_t)(kb + kk) * HH + n0 + c];
            W1s[kk][c] = W1[(size_t)(kb + kk) * HH + n0 + c];
        }
        __syncthreads();
#pragma unroll 16
        for (int kk = 0; kk < 64; kk++) {
            float w0 = W0s[kk][col], w1 = W1s[kk][col];
#pragma unroll
            for (int i = 0; i < 4; i++) {
                float a = Hs[kk][rowbase + i];
                a0[i] = fmaf(a, w0, a0[i]);
                a1[i] = fmaf(a, w1, a1[i]);
            }
        }
        __syncthreads();
    }
    float bb0 = b0v[n0 + col], bb1 = b1v[n0 + col];
#pragma unroll
    for (int i = 0; i < 4; i++) {
        int m = rowbase + i, n = n0 + col;
        out0[(size_t)m * HH + n] = a0[i] + bb0;
        out1[(size_t)m * HH + n] = a1[i] + bb1;
    }
}

// ======================= persistent HMMA recurrence v3 ==================
// 64 CTAs x 16 cols. W-hi in smem, W-lo in regs, double-buffered h staging.
#define WSTR   1032
#define WMAT_B (16*WSTR*2)           // 33024
#define W_REGION (2*WMAT_B)          // 66048
#define HSTR3  264
#define HPL_B  (64*HSTR3*2)          // 33792
#define HBUF_B (2*HPL_B)             // 67584
#define RSMEM3 (W_REGION + 2*HBUF_B) // 201216
__global__ __launch_bounds__(256, 1) void rec_hmma(
    const float* __restrict__ h0,
    const __nv_bfloat16* __restrict__ wrh, const __nv_bfloat16* __restrict__ wrl,
    const __nv_bfloat16* __restrict__ w1h, const __nv_bfloat16* __restrict__ w1l,
    const float* __restrict__ bhr, const float* __restrict__ bh1,
    const float* __restrict__ x0r, const float* __restrict__ x0z,
    const float* __restrict__ xtz, const float* __restrict__ xth1,
    float* __restrict__ hts,
    __nv_bfloat16* __restrict__ hs_h, __nv_bfloat16* __restrict__ hs_l)
{
    extern __shared__ __align__(16) char rsm[];
    const uint32_t sb = smem_u32(rsm);
    float* red = (float*)(rsm + W_REGION);            // overlays hbuf0
    float* fin = (float*)(rsm + W_REGION + HBUF_B);   // overlays hbuf1

    const int tid = threadIdx.x;
    const int w = tid >> 5, l = tid & 31;
    const int n0 = blockIdx.x * 16;

    // ---- W-hi into smem (cp.async, coalesced from packed [N][K]) ----
#pragma unroll
    for (int g = 0; g < 2; g++) {
        const __nv_bfloat16* src = g ? w1h : wrh;
        for (int i = tid; i < 2048; i += 256) {       // 16 rows x 128 segs
            int row = i >> 7, seg = i & 127;
            cpa16(sb + g * WMAT_B + (uint32_t)(row * WSTR + seg * 8) * 2,
                  src + (size_t)(n0 + row) * HH + seg * 8);
        }
    }
    CP_COMMIT(); CP_WAIT(0);

    // ---- W-lo into registers (b-frag lane map) ----
    uint32_t wlo[8][2][4];
#pragma unroll
    for (int r = 0; r < 4; r++)
#pragma unroll
        for (int s = 0; s < 2; s++) {
            int j = r * 2 + s;
            int kg = r * 256 + w * 32 + s * 16;
#pragma unroll
            for (int g = 0; g < 2; g++) {
                const __nv_bfloat16* Wl = g ? w1l : wrl;
#pragma unroll
                for (int q = 0; q < 4; q++) {
                    int nq = n0 + (q & 1) * 8 + (l >> 2);
                    int kq = kg + (q >> 1) * 8 + (l & 3) * 2;
                    wlo[j][g][q] = *(const uint32_t*)(Wl + (size_t)nq * HH + kq);
                }
            }
        }

    // epilogue constants: thread owns row = tid>>2, cols nl0..nl0+3
    const int erow = tid >> 2, nl0 = (tid & 3) * 4;
    float xr[4], xz[4], b1c[4], hp[4];
#pragma unroll
    for (int i = 0; i < 4; i++) {
        int n = n0 + nl0 + i;
        xr[i]  = bhr[n] + x0r[(size_t)erow * HH + n];
        xz[i]  = x0z[(size_t)erow * HH + n];
        b1c[i] = bh1[n];
        hp[i]  = h0[(size_t)erow * HH + n];
    }
    const int crow = tid >> 2, ccol0 = (tid & 3) * 8;

    for (int t = 0; t < SS; t++) {
        const int slot_in  = (t + 1) & 1;    // h0 pre-split into slot 1
        const int slot_out = t & 1;
        const __nv_bfloat16* shp = hs_h + (size_t)slot_in * BB * HH;
        const __nv_bfloat16* slp = hs_l + (size_t)slot_in * BB * HH;

        float acc[4][2][2][4];
#pragma unroll
        for (int mt = 0; mt < 4; mt++)
#pragma unroll
            for (int g = 0; g < 2; g++)
#pragma unroll
                for (int sub = 0; sub < 2; sub++)
#pragma unroll
                    for (int e = 0; e < 4; e++) acc[mt][g][sub][e] = 0.f;

        // prologue: stage round 0 into buf 0
        {
#pragma unroll
            for (int q = 0; q < 8; q++) {
                int c = ccol0 + q * 32;
                uint32_t d = sb + W_REGION + (uint32_t)(crow * HSTR3 + c) * 2;
                cpa16(d,         shp + (size_t)crow * HH + c);
                cpa16(d + HPL_B, slp + (size_t)crow * HH + c);
            }
            CP_COMMIT();
        }

#pragma unroll
        for (int r = 0; r < 4; r++) {
            if (r < 3) {
                const int buf = (r + 1) & 1;
                const int gc = (r + 1) * 256;
#pragma unroll
                for (int q = 0; q < 8; q++) {
                    int c = ccol0 + q * 32;
                    uint32_t d = sb + W_REGION + buf * HBUF_B
                               + (uint32_t)(crow * HSTR3 + c) * 2;
                    cpa16(d,         shp + (size_t)crow * HH + gc + c);
                    cpa16(d + HPL_B, slp + (size_t)crow * HH + gc + c);
                }
                CP_COMMIT();
                CP_WAIT(1);
            } else {
                CP_WAIT(0);
            }
            __syncthreads();

            const uint32_t abase = sb + W_REGION + (uint32_t)(r & 1) * HBUF_B;
#pragma unroll
            for (int s = 0; s < 2; s++) {
                const int j = r * 2 + s;
                const int kg = r * 256 + w * 32 + s * 16;
                const int kl = w * 32 + s * 16;
                uint32_t fw[2][4];
#pragma unroll
                for (int g = 0; g < 2; g++)
                    ldsm_x4(fw[g], sb + g * WMAT_B
                            + (uint32_t)((l & 15) * WSTR + kg + (l >> 4) * 8) * 2);
#pragma unroll
                for (int mt = 0; mt < 4; mt++) {
                    uint32_t ah = abase + (uint32_t)((mt * 16 + (l & 15)) * HSTR3
                                 + kl + (l >> 4) * 8) * 2;
                    uint32_t fa[4], fl[4];
                    ldsm_x4(fa, ah);
                    ldsm_x4(fl, ah + HPL_B);
#pragma unroll
                    for (int g = 0; g < 2; g++)
#pragma unroll
                        for (int sub = 0; sub < 2; sub++) {
                            mma16816(acc[mt][g][sub], fa, fw[g][sub], fw[g][2 + sub]);
                            mma16816(acc[mt][g][sub], fa, wlo[j][g][sub], wlo[j][g][2 + sub]);
                            mma16816(acc[mt][g][sub], fl, fw[g][sub], fw[g][2 + sub]);
                        }
                }
            }
            __syncthreads();
        }

        // cross-warp K reduction (8 partials per output)
        {
            float* my = red + (size_t)tid * 64;
#pragma unroll
            for (int mt = 0; mt < 4; mt++)
#pragma unroll
                for (int g = 0; g < 2; g++)
#pragma unroll
                    for (int sub = 0; sub < 2; sub++)
#pragma unroll
                        for (int e = 0; e < 4; e++)
                            my[((mt*2 + g)*2 + sub)*4 + e] = acc[mt][g][sub][e];
        }
        __syncthreads();
#pragma unroll
        for (int gi = 0; gi < 2; gi++) {
            int idx4 = tid * 2 + gi;
            int l2 = idx4 >> 4, i4 = (idx4 & 15) * 4;
            float4 s4 = make_float4(0.f, 0.f, 0.f, 0.f);
#pragma unroll
            for (int ww = 0; ww < 8; ww++) {
                float4 p = *(const float4*)(red + ((size_t)(ww*32 + l2))*64 + i4);
                s4.x += p.x; s4.y += p.y; s4.z += p.z; s4.w += p.w;
            }
            *(float4*)(fin + l2*64 + i4) = s4;
        }
        __syncthreads();

        // fused GRU epilogue (4 outputs per thread, same row)
        {
            size_t mtn0 = ((size_t)erow * SS + t) * HH + n0 + nl0;
            float4 xtzv = *(const float4*)(xtz  + mtn0);
            float4 xthv = *(const float4*)(xth1 + mtn0);
            float xtza[4] = {xtzv.x, xtzv.y, xtzv.z, xtzv.w};
            float xtha[4] = {xthv.x, xthv.y, xthv.z, xthv.w};
            float outv[4];
            unsigned short hb4[4], lb4[4];
            const int mt = erow >> 4, r4 = erow & 15;
#pragma unroll
            for (int i = 0; i < 4; i++) {
                int nl = nl0 + i;
                int l2 = (r4 & 7) * 4 + ((nl & 7) >> 1);
                int e  = ((r4 >> 3) << 1) + (nl & 1);
                int sub = nl >> 3;
                float ar = fin[l2*64 + ((mt*2 + 0)*2 + sub)*4 + e];
                float a1 = fin[l2*64 + ((mt*2 + 1)*2 + sub)*4 + e];
                float rg = 1.f / (1.f + expf(-(ar + xr[i])));
                float zg = 1.f / (1.f + expf(-(xtza[i] + xz[i])));
                float t1 = tanhf(xtha[i] + rg * (a1 + b1c[i]));
                float ht = (1.f - zg) * t1 + zg * hp[i];
                hp[i] = ht;
                outv[i] = ht;
                __nv_bfloat16 hb = __float2bfloat16(ht);
                __nv_bfloat16 lb = __float2bfloat16(ht - __bfloat162float(hb));
                hb4[i] = *(unsigned short*)&hb;
                lb4[i] = *(unsigned short*)&lb;
            }
            *(float4*)(hts + mtn0) = make_float4(outv[0], outv[1], outv[2], outv[3]);
            size_t ho = (size_t)slot_out * BB * HH + (size_t)erow * HH + n0 + nl0;
            *(uint2*)(hs_h + ho) = make_uint2((uint32_t)hb4[0] | ((uint32_t)hb4[1] << 16),
                                              (uint32_t)hb4[2] | ((uint32_t)hb4[3] << 16));
            *(uint2*)(hs_l + ho) = make_uint2((uint32_t)lb4[0] | ((uint32_t)lb4[1] << 16),
                                              (uint32_t)lb4[2] | ((uint32_t)lb4[3] << 16));
        }

        __threadfence();
        __syncthreads();
        if (tid == 0) {
            atomicAdd(&g_bar, 1);
            const int target = 64 * (t + 1);
            while (*(volatile int*)&g_bar < target) { }
        }
        __syncthreads();
    }

    if (tid == 0) atomicAdd(&g_ack, 1);
    if (blockIdx.x == 0 && tid == 0) {
        while (*(volatile int*)&g_ack < 64) { }
        g_bar = 0;
        g_ack = 0;
        __threadfence();
    }
}

// ======================= host launcher =======================
extern "C" void kernel_launch(void* const* d_in, const int* in_sizes, int n_in,
                              void* d_out, int out_size)
{
    const float* x     = (const float*)d_in[0];
    const float* h0    = (const float*)d_in[1];
    const float* Wxe   = (const float*)d_in[2];
    const float* bxe   = (const float*)d_in[3];
    const float* Wep   = (const float*)d_in[4];
    const float* bep   = (const float*)d_in[5];
    const float* Whr   = (const float*)d_in[6];
    const float* bhr   = (const float*)d_in[7];
    const float* Wx0r  = (const float*)d_in[8];
    const float* bx0r  = (const float*)d_in[9];
    const float* Wxtz  = (const float*)d_in[10];
    const float* bxtz  = (const float*)d_in[11];
    const float* Wx0z  = (const float*)d_in[12];
    const float* bx0z  = (const float*)d_in[13];
    const float* Wxth1 = (const float*)d_in[14];
    const float* bxth1 = (const float*)d_in[15];
    const float* Wh1h1 = (const float*)d_in[16];
    const float* bh1h1 = (const float*)d_in[17];

    float* out  = (float*)d_out;
    float* hts  = out;
    float* ptes = hts  + (size_t)BB*SS*HH;
    float* p0es = ptes + (size_t)BB*SS*CC;
    float* xtes = p0es + (size_t)BB*SS*CC;
    float* x0es = xtes + (size_t)BB*SS*HH;

    float *p_xtz, *p_xth1, *p_x0r, *p_x0z;
    __nv_bfloat16 *x_h, *x_l, *wxe_h, *wxe_l, *e_h, *e_l, *wz_h, *wz_l, *wh_h, *wh_l;
    __nv_bfloat16 *wr_h, *wr_l, *w1_h, *w1_l, *hs_h, *hs_l;
    cudaGetSymbolAddress((void**)&p_xtz,  g_xtz);
    cudaGetSymbolAddress((void**)&p_xth1, g_xth1);
    cudaGetSymbolAddress((void**)&p_x0r,  g_x0r);
    cudaGetSymbolAddress((void**)&p_x0z,  g_x0z);
    cudaGetSymbolAddress((void**)&x_h,    g_x_h);
    cudaGetSymbolAddress((void**)&x_l,    g_x_l);
    cudaGetSymbolAddress((void**)&wxe_h,  g_wxe_h);
    cudaGetSymbolAddress((void**)&wxe_l,  g_wxe_l);
    cudaGetSymbolAddress((void**)&e_h,    g_e_h);
    cudaGetSymbolAddress((void**)&e_l,    g_e_l);
    cudaGetSymbolAddress((void**)&wz_h,   g_wz_h);
    cudaGetSymbolAddress((void**)&wz_l,   g_wz_l);
    cudaGetSymbolAddress((void**)&wh_h,   g_wh_h);
    cudaGetSymbolAddress((void**)&wh_l,   g_wh_l);
    cudaGetSymbolAddress((void**)&wr_h,   g_wr_h);
    cudaGetSymbolAddress((void**)&wr_l,   g_wr_l);
    cudaGetSymbolAddress((void**)&w1_h,   g_w1_h);
    cudaGetSymbolAddress((void**)&w1_l,   g_w1_l);
    cudaGetSymbolAddress((void**)&hs_h,   g_hs_h);
    cudaGetSymbolAddress((void**)&hs_l,   g_hs_l);

    cudaFuncSetAttribute(hmma_gemm, cudaFuncAttributeMaxDynamicSharedMemorySize, 2 * STG_B);
    cudaFuncSetAttribute(rec_hmma,  cudaFuncAttributeMaxDynamicSharedMemorySize, RSMEM3);

    // launch order: gemm1 at index 3 (profiled slot)
    pack_rm<<<(MM*FF/4 + 255)/256, 256>>>(x, x_h, x_l, MM*FF);                 // 0
    pack_tr<<<dim3(HH/32, FF/32), 256>>>(Wxe, wxe_h, wxe_l, FF, HH);           // 1
    pack_h0<<<(BB*HH/4 + 255)/256, 256>>>(h0, hs_h + (size_t)BB*HH,            // 2
                                          hs_l + (size_t)BB*HH);
    hmma_gemm<<<dim3(HH/128, MM/128), 256, 2*STG_B>>>(                         // 3
        x_h, x_l, wxe_h, wxe_l, bxe, xtes, MM, HH, FF, 1, e_h, e_l, x0es);

    pack_tr<<<dim3(HH/32, HH/32), 256>>>(Wxtz,  wz_h, wz_l, HH, HH);           // 4
    pack_tr<<<dim3(HH/32, HH/32), 256>>>(Wxth1, wh_h, wh_l, HH, HH);           // 5
    pack_tr<<<dim3(HH/32, HH/32), 256>>>(Whr,   wr_h, wr_l, HH, HH);           // 6
    pack_tr<<<dim3(HH/32, HH/32), 256>>>(Wh1h1, w1_h, w1_l, HH, HH);           // 7
    ptes_kernel<<<MM/8, 256>>>(xtes, Wep, bep, ptes);                          // 8
    bcast_p0es<<<(BB*SS*CC + 255)/256, 256>>>(ptes, p0es);                     // 9

    hmma_gemm<<<dim3(HH/128, MM/128), 256, 2*STG_B>>>(                         // 10
        e_h, e_l, wz_h, wz_l, bxtz, p_xtz, MM, HH, HH, 0,
        (__nv_bfloat16*)0, (__nv_bfloat16*)0, (float*)0);
    hmma_gemm<<<dim3(HH/128, MM/128), 256, 2*STG_B>>>(                         // 11
        e_h, e_l, wh_h, wh_l, bxth1, p_xth1, MM, HH, HH, 0,
        (__nv_bfloat16*)0, (__nv_bfloat16*)0, (float*)0);

    dual64_kernel<<<HH/16, 256>>>(xtes + (size_t)(SS-1)*HH, SS*HH,             // 12
                                  Wx0r, Wx0z, bx0r, bx0z, p_x0r, p_x0z);

    rec_hmma<<<64, 256, RSMEM3>>>(h0, wr_h, wr_l, w1_h, w1_l, bhr, bh1h1 ? bh1h1 : bh1h1, // 13
                                  p_x0r, p_x0z, p_xtz, p_xth1,
                                  hts, hs_h, hs_l);
}

// round 14
// speedup vs baseline: 1.0981x; 1.0981x over previous
#include <cuda_runtime.h>
#include <cuda_bf16.h>
#include <cstdint>
#include <math.h>

#define BB 64
#define SS 64
#define FF 4096
#define HH 1024
#define CC 31
#define MM (BB*SS)

__device__ float g_xtz [MM*HH];
__device__ float g_xth1[MM*HH];
__device__ float g_x0r [BB*HH];
__device__ float g_x0z [BB*HH];
__device__ int   g_bar = 0;
__device__ int   g_ack = 0;

__device__ __align__(16) __nv_bfloat16 g_x_h  [MM*FF];
__device__ __align__(16) __nv_bfloat16 g_x_l  [MM*FF];
__device__ __align__(16) __nv_bfloat16 g_wxe_h[HH*FF];
__device__ __align__(16) __nv_bfloat16 g_wxe_l[HH*FF];
__device__ __align__(16) __nv_bfloat16 g_e_h  [MM*HH];
__device__ __align__(16) __nv_bfloat16 g_e_l  [MM*HH];
__device__ __align__(16) __nv_bfloat16 g_wz_h [HH*HH];
__device__ __align__(16) __nv_bfloat16 g_wz_l [HH*HH];
__device__ __align__(16) __nv_bfloat16 g_wh_h [HH*HH];
__device__ __align__(16) __nv_bfloat16 g_wh_l [HH*HH];
__device__ __align__(16) __nv_bfloat16 g_hs_h [2*BB*HH];
__device__ __align__(16) __nv_bfloat16 g_hs_l [2*BB*HH];

__device__ __forceinline__ uint32_t smem_u32(const void* p) {
    uint32_t a;
    asm("{ .reg .u64 t; cvta.to.shared.u64 t, %1; cvt.u32.u64 %0, t; }"
        : "=r"(a) : "l"(p));
    return a;
}
__device__ __forceinline__ void ldsm_x4(uint32_t* r, uint32_t addr) {
    asm volatile("ldmatrix.sync.aligned.m8n8.x4.shared.b16 {%0,%1,%2,%3}, [%4];"
        : "=r"(r[0]), "=r"(r[1]), "=r"(r[2]), "=r"(r[3]) : "r"(addr));
}
__device__ __forceinline__ void mma16816(float* d, const uint32_t* a, uint32_t b0, uint32_t b1) {
    asm volatile(
        "mma.sync.aligned.m16n8k16.row.col.f32.bf16.bf16.f32 "
        "{%0,%1,%2,%3}, {%4,%5,%6,%7}, {%8,%9}, {%0,%1,%2,%3};"
        : "+f"(d[0]), "+f"(d[1]), "+f"(d[2]), "+f"(d[3])
        : "r"(a[0]), "r"(a[1]), "r"(a[2]), "r"(a[3]), "r"(b0), "r"(b1));
}
__device__ __forceinline__ void cpa16(uint32_t dst, const void* src) {
    asm volatile("cp.async.ca.shared.global [%0], [%1], 16;" :: "r"(dst), "l"(src));
}
__device__ __forceinline__ void cpa16_cg(uint32_t dst, const void* src) {
    asm volatile("cp.async.cg.shared.global [%0], [%1], 16;" :: "r"(dst), "l"(src));
}
#define CP_COMMIT() asm volatile("cp.async.commit_group;")
#define CP_WAIT(N)  asm volatile("cp.async.wait_group %0;" :: "n"(N))

__device__ __forceinline__ void split2(float a, float b, uint32_t& hi, uint32_t& lo) {
    __nv_bfloat16 ha = __float2bfloat16(a);
    __nv_bfloat16 hb = __float2bfloat16(b);
    __nv_bfloat16 la = __float2bfloat16(a - __bfloat162float(ha));
    __nv_bfloat16 lb = __float2bfloat16(b - __bfloat162float(hb));
    unsigned short uha = *(unsigned short*)&ha, uhb = *(unsigned short*)&hb;
    unsigned short ula = *(unsigned short*)&la, ulb = *(unsigned short*)&lb;
    hi = (uint32_t)uha | ((uint32_t)uhb << 16);
    lo = (uint32_t)ula | ((uint32_t)ulb << 16);
}

// ======================= pack =======================
__global__ __launch_bounds__(256) void pack_rm(
    const float* __restrict__ src,
    __nv_bfloat16* __restrict__ dh, __nv_bfloat16* __restrict__ dl, int n)
{
    int i = (blockIdx.x * 256 + threadIdx.x) * 4;
    if (i < n) {
        float4 v = *(const float4*)(src + i);
        uint32_t h0, l0, h1, l1;
        split2(v.x, v.y, h0, l0);
        split2(v.z, v.w, h1, l1);
        *(uint2*)(dh + i) = make_uint2(h0, h1);
        *(uint2*)(dl + i) = make_uint2(l0, l1);
    }
}

__global__ __launch_bounds__(256) void pack_tr(
    const float* __restrict__ src,
    __nv_bfloat16* __restrict__ dh, __nv_bfloat16* __restrict__ dl,
    int Kd, int Nd)
{
    __shared__ float t[32][33];
    int n0 = blockIdx.x * 32, k0 = blockIdx.y * 32;
    int tx = threadIdx.x & 31, ty = threadIdx.x >> 5;
#pragma unroll
    for (int r = 0; r < 4; r++)
        t[ty + r*8][tx] = src[(size_t)(k0 + ty + r*8) * Nd + n0 + tx];
    __syncthreads();
#pragma unroll
    for (int r = 0; r < 4; r++) {
        int nr = ty + r * 8;
        float v = t[tx][nr];
        __nv_bfloat16 hb = __float2bfloat16(v);
        __nv_bfloat16 lb = __float2bfloat16(v - __bfloat162float(hb));
        size_t o = (size_t)(n0 + nr) * Kd + k0 + tx;
        dh[o] = hb;
        dl[o] = lb;
    }
}

__global__ __launch_bounds__(256) void pack_h0(
    const float* __restrict__ h0,
    __nv_bfloat16* __restrict__ dh, __nv_bfloat16* __restrict__ dl)
{
    int i = (blockIdx.x * 256 + threadIdx.x) * 4;
    if (i < BB * HH) {
        float4 v = *(const float4*)(h0 + i);
        uint32_t hx0, lx0, hx1, lx1;
        split2(v.x, v.y, hx0, lx0);
        split2(v.z, v.w, hx1, lx1);
        *(uint2*)(dh + i) = make_uint2(hx0, hx1);
        *(uint2*)(dl + i) = make_uint2(lx0, lx1);
    }
}

// ======================= hmma_gemm (validated; optional dual-N merge) ===
#define ASTR 40
#define MAT_B (128*ASTR*2)
#define STG_B (4*MAT_B)
__global__ __launch_bounds__(256, 2) void hmma_gemm(
    const __nv_bfloat16* __restrict__ Ah, const __nv_bfloat16* __restrict__ Al,
    const __nv_bfloat16* __restrict__ Bh, const __nv_bfloat16* __restrict__ Bl,
    const float* __restrict__ bias, float* __restrict__ C,
    int M, int N, int K, int relu,
    __nv_bfloat16* __restrict__ Ch, __nv_bfloat16* __restrict__ Cl,
    float* __restrict__ x0es,
    const __nv_bfloat16* __restrict__ B2h, const __nv_bfloat16* __restrict__ B2l,
    const float* __restrict__ bias2, float* __restrict__ C2)
{
    extern __shared__ __align__(16) char sm[];
    const uint32_t sbase = smem_u32(sm);
    const int tid = threadIdx.x, wid = tid >> 5, lane = tid & 31;
    const int warp_m = wid & 1, warp_n = wid >> 1;

    // dual-N merge: upper half of grid.x uses the second B/bias/C set
    int bx = blockIdx.x;
    const __nv_bfloat16* pBh = Bh;
    const __nv_bfloat16* pBl = Bl;
    const float* pbias = bias;
    float* pC = C;
    if (B2h) {
        int half = gridDim.x >> 1;
        if (bx >= half) { bx -= half; pBh = B2h; pBl = B2l; pbias = bias2; pC = C2; }
    }
    const int m0 = blockIdx.y * 128, n0 = bx * 128;
    const int lrow = lane & 15, lhalf = lane >> 4;

    const int crow = tid >> 1, cseg = tid & 1;
    const __nv_bfloat16* gAh = Ah + (size_t)(m0 + crow) * K + cseg * 16;
    const __nv_bfloat16* gAl = Al + (size_t)(m0 + crow) * K + cseg * 16;
    const __nv_bfloat16* gBh = pBh + (size_t)(n0 + crow) * K + cseg * 16;
    const __nv_bfloat16* gBl = pBl + (size_t)(n0 + crow) * K + cseg * 16;
    const uint32_t dbase = sbase + (uint32_t)(crow * ASTR + cseg * 16) * 2;

    uint32_t offA[4], offB[2];
#pragma unroll
    for (int mt = 0; mt < 4; mt++)
        offA[mt] = sbase + (uint32_t)((warp_m * 64 + mt * 16 + lrow) * ASTR + lhalf * 8) * 2;
#pragma unroll
    for (int np = 0; np < 2; np++)
        offB[np] = sbase + 2 * MAT_B
                 + (uint32_t)((warp_n * 32 + np * 16 + lrow) * ASTR + lhalf * 8) * 2;

    float acc[4][4][4];
#pragma unroll
    for (int i = 0; i < 4; i++)
#pragma unroll
        for (int j = 0; j < 4; j++)
#pragma unroll
            for (int e = 0; e < 4; e++) acc[i][j][e] = 0.f;

    const int nk = K >> 5;
    {
        uint32_t d = dbase;
        cpa16(d,           gAh); cpa16(d + 16,           gAh + 8);
        cpa16(d + MAT_B,   gAl); cpa16(d + MAT_B + 16,   gAl + 8);
        cpa16(d + 2*MAT_B, gBh); cpa16(d + 2*MAT_B + 16, gBh + 8);
        cpa16(d + 3*MAT_B, gBl); cpa16(d + 3*MAT_B + 16, gBl + 8);
        CP_COMMIT();
    }
    for (int kc = 0; kc < nk; kc++) {
        if (kc + 1 < nk) {
            uint32_t d = dbase + ((kc + 1) & 1) * STG_B;
            const int go = (kc + 1) * 32;
            cpa16(d,           gAh + go); cpa16(d + 16,           gAh + go + 8);
            cpa16(d + MAT_B,   gAl + go); cpa16(d + MAT_B + 16,   gAl + go + 8);
            cpa16(d + 2*MAT_B, gBh + go); cpa16(d + 2*MAT_B + 16, gBh + go + 8);
            cpa16(d + 3*MAT_B, gBl + go); cpa16(d + 3*MAT_B + 16, gBl + go + 8);
            CP_COMMIT();
            CP_WAIT(1);
        } else {
            CP_WAIT(0);
        }
        __syncthreads();
        const uint32_t stb = (kc & 1) * STG_B;
#pragma unroll
        for (int ks = 0; ks < 2; ks++) {
            const uint32_t ko = stb + ks * 32;
            uint32_t fah[4][4], fal[4][4], fbh[2][4], fbl[2][4];
#pragma unroll
            for (int mt = 0; mt < 4; mt++) {
                ldsm_x4(fah[mt], offA[mt] + ko);
                ldsm_x4(fal[mt], offA[mt] + ko + MAT_B);
            }
#pragma unroll
            for (int np = 0; np < 2; np++) {
                ldsm_x4(fbh[np], offB[np] + ko);
                ldsm_x4(fbl[np], offB[np] + ko + MAT_B);
            }
#pragma unroll
            for (int mt = 0; mt < 4; mt++) {
#pragma unroll
                for (int ni = 0; ni < 4; ni++) {
                    const int np = ni >> 1, sub = ni & 1;
                    mma16816(acc[mt][ni], fah[mt], fbh[np][sub], fbh[np][2 + sub]);
                    mma16816(acc[mt][ni], fah[mt], fbl[np][sub], fbl[np][2 + sub]);
                    mma16816(acc[mt][ni], fal[mt], fbh[np][sub], fbh[np][2 + sub]);
                }
            }
        }
        __syncthreads();
    }
#pragma unroll
    for (int mt = 0; mt < 4; mt++) {
#pragma unroll
        for (int ni = 0; ni < 4; ni++) {
            int row = m0 + warp_m * 64 + mt * 16 + (lane >> 2);
            int col = n0 + warp_n * 32 + ni * 8 + (lane & 3) * 2;
            float b0 = __ldg(&pbias[col]), b1 = __ldg(&pbias[col + 1]);
            float v0 = acc[mt][ni][0] + b0;
            float v1 = acc[mt][ni][1] + b1;
            float v2 = acc[mt][ni][2] + b0;
            float v3 = acc[mt][ni][3] + b1;
            if (relu) {
                v0 = fmaxf(v0, 0.f); v1 = fmaxf(v1, 0.f);
                v2 = fmaxf(v2, 0.f); v3 = fmaxf(v3, 0.f);
            }
            *(float2*)(pC + (size_t)row * N + col)       = make_float2(v0, v1);
            *(float2*)(pC + (size_t)(row + 8) * N + col) = make_float2(v2, v3);
            if (Ch) {
                uint32_t h0, l0, h1, l1;
                split2(v0, v1, h0, l0);
                split2(v2, v3, h1, l1);
                *(uint32_t*)(Ch + (size_t)row * N + col)       = h0;
                *(uint32_t*)(Cl + (size_t)row * N + col)       = l0;
                *(uint32_t*)(Ch + (size_t)(row + 8) * N + col) = h1;
                *(uint32_t*)(Cl + (size_t)(row + 8) * N + col) = l1;
            }
            if (x0es && (((row + 8) & 63) == 63)) {
                int base = ((row + 8) >> 6) << 6;
#pragma unroll 4
                for (int s = 0; s < SS; s++)
                    *(float2*)(x0es + (size_t)(base + s) * N + col) = make_float2(v2, v3);
            }
        }
    }
}

// ======================= ptes / bcast / dual64 =======================
__global__ __launch_bounds__(256) void ptes_kernel(
    const float* __restrict__ xtes, const float* __restrict__ Wep,
    const float* __restrict__ bep, float* __restrict__ ptes)
{
    __shared__ float Weps[256][32];
    __shared__ float xs[8][256];
    int tid  = threadIdx.x;
    int row0 = blockIdx.x * 8;
    int warp = tid >> 5, lane = tid & 31;
    float acc = 0.f;
    for (int kb = 0; kb < HH; kb += 256) {
        for (int i = tid; i < 256 * CC; i += 256) {
            int kk = i / CC, c = i % CC;
            Weps[kk][c] = Wep[(size_t)(kb + kk) * CC + c];
        }
        for (int i = tid; i < 8 * 256; i += 256) {
            int r = i >> 8, kk = i & 255;
            xs[r][kk] = xtes[(size_t)(row0 + r) * HH + kb + kk];
        }
        __syncthreads();
        if (lane < CC) {
#pragma unroll 8
            for (int kk = 0; kk < 256; kk++)
                acc = fmaf(xs[warp][kk], Weps[kk][lane], acc);
        }
        __syncthreads();
    }
    if (lane < CC)
        ptes[(size_t)(row0 + warp) * CC + lane] = acc + bep[lane];
}

__global__ void bcast_p0es(const float* __restrict__ ptes, float* __restrict__ p0es)
{
    int idx = blockIdx.x * blockDim.x + threadIdx.x;
    if (idx < BB * SS * CC) {
        int c  = idx % CC;
        int b  = (idx / CC) / SS;
        p0es[idx] = ptes[(size_t)(b * SS + (SS - 1)) * CC + c];
    }
}

__global__ __launch_bounds__(256) void dual64_kernel(
    const float* __restrict__ A, int lda,
    const float* __restrict__ W0, const float* __restrict__ W1,
    const float* __restrict__ b0v, const float* __restrict__ b1v,
    float* __restrict__ out0, float* __restrict__ out1)
{
    __shared__ float Hs[64][65];
    __shared__ float W0s[64][16];
    __shared__ float W1s[64][16];
    int tid = threadIdx.x;
    int n0  = blockIdx.x * 16;
    int col = tid & 15;
    int rowbase = (tid >> 4) * 4;
    float a0[4] = {0,0,0,0}, a1[4] = {0,0,0,0};
    for (int kb = 0; kb < HH; kb += 64) {
#pragma unroll
        for (int i = 0; i < 4; i++) {
            int lin = tid + i * 256;
            int m = lin >> 4, kq = lin & 15;
            float4 v = *(const float4*)(A + (size_t)m * lda + kb + kq * 4);
            Hs[kq*4+0][m] = v.x; Hs[kq*4+1][m] = v.y;
            Hs[kq*4+2][m] = v.z; Hs[kq*4+3][m] = v.w;
        }
#pragma unroll
        for (int i = 0; i < 4; i++) {
            int lin = tid + i * 256;
            int kk = lin >> 4, c = lin & 15;
            W0s[kk][c] = W0[(size_t)(kb + kk) * HH + n0 + c];
            W1s[kk][c] = W1[(size_t)(kb + kk) * HH + n0 + c];
        }
        __syncthreads();
#pragma unroll 16
        for (int kk = 0; kk < 64; kk++) {
            float w0 = W0s[kk][col], w1 = W1s[kk][col];
#pragma unroll
            for (int i = 0; i < 4; i++) {
                float a = Hs[kk][rowbase + i];
                a0[i] = fmaf(a, w0, a0[i]);
                a1[i] = fmaf(a, w1, a1[i]);
            }
        }
        __syncthreads();
    }
    float bb0 = b0v[n0 + col], bb1 = b1v[n0 + col];
#pragma unroll
    for (int i = 0; i < 4; i++) {
        int m = rowbase + i, n = n0 + col;
        out0[(size_t)m * HH + n] = a0[i] + bb0;
        out1[(size_t)m * HH + n] = a1[i] + bb1;
    }
}

// ======================= persistent HMMA recurrence (R12-validated) =====
#define HSTRIDE 520
#define HBYTES  (64*HSTRIDE*2)
#define RSMEM_H (2*HBYTES)
__global__ __launch_bounds__(256, 1) void rec_hmma(
    const float* __restrict__ h0,
    const float* __restrict__ Whr, const float* __restrict__ Wh1,
    const float* __restrict__ bhr, const float* __restrict__ bh1,
    const float* __restrict__ x0r, const float* __restrict__ x0z,
    const float* __restrict__ xtz, const float* __restrict__ xth1,
    float* __restrict__ hts,
    __nv_bfloat16* __restrict__ hs_h, __nv_bfloat16* __restrict__ hs_l)
{
    extern __shared__ __align__(16) char rsm[];
    const uint32_t sb = smem_u32(rsm);
    float* red = (float*)rsm;
    float* fin = (float*)(rsm + 32768);

    const int tid = threadIdx.x;
    const int w = tid >> 5, l = tid & 31;
    const int n0 = blockIdx.x * 8;

    uint32_t wreg[8][2][2][2];
#pragma unroll
    for (int r = 0; r < 2; r++)
#pragma unroll
        for (int j = 0; j < 4; j++) {
            int kb = (r*32 + w + 8*j) * 16 + (l & 3) * 2;
            int nc = n0 + (l >> 2);
#pragma unroll
            for (int g = 0; g < 2; g++) {
                const float* Wp = g ? Wh1 : Whr;
#pragma unroll
                for (int hf = 0; hf < 2; hf++) {
                    float v0 = Wp[(size_t)(kb + hf*8)     * HH + nc];
                    float v1 = Wp[(size_t)(kb + hf*8 + 1) * HH + nc];
                    uint32_t hi, lo; split2(v0, v1, hi, lo);
                    wreg[r*4+j][g][0][hf] = hi;
                    wreg[r*4+j][g][1][hf] = lo;
                }
            }
        }

    float xr[2], xz[2], b1c[2], hp[2];
    int prow[2], pnl[2];
#pragma unroll
    for (int i = 0; i < 2; i++) {
        int p = tid * 2 + i, row = p >> 3, nl = p & 7, n = n0 + nl;
        prow[i] = row; pnl[i] = nl;
        xr[i]  = bhr[n] + x0r[(size_t)row * HH + n];
        xz[i]  = x0z[(size_t)row * HH + n];
        b1c[i] = bh1[n];
        hp[i]  = h0[(size_t)row * HH + n];
    }
    const int crow = tid >> 2, ccol0 = (tid & 3) * 8;

    for (int t = 0; t < SS; t++) {
        const int slot_in  = (t + 1) & 1;
        const int slot_out = t & 1;
        const __nv_bfloat16* sh_in = hs_h + (size_t)slot_in * BB * HH;
        const __nv_bfloat16* sl_in = hs_l + (size_t)slot_in * BB * HH;

        float acc[4][2][4];
#pragma unroll
        for (int mt = 0; mt < 4; mt++)
#pragma unroll
            for (int g = 0; g < 2; g++)
#pragma unroll
                for (int e = 0; e < 4; e++) acc[mt][g][e] = 0.f;

#pragma unroll
        for (int r = 0; r < 2; r++) {
            {
                const size_t gbase = (size_t)crow * HH + r * 512;
#pragma unroll
                for (int q = 0; q < 16; q++) {
                    int c = ccol0 + q * 32;
                    uint32_t d = sb + (uint32_t)(crow * HSTRIDE + c) * 2;
                    cpa16_cg(d,          sh_in + gbase + c);
                    cpa16_cg(d + HBYTES, sl_in + gbase + c);
                }
                CP_COMMIT();
                CP_WAIT(0);
            }
            __syncthreads();
#pragma unroll
            for (int j = 0; j < 4; j++) {
                const int klocal = (w + 8*j) * 16;
#pragma unroll
                for (int mt = 0; mt < 4; mt++) {
                    uint32_t ah = sb + (uint32_t)((mt*16 + (l & 15)) * HSTRIDE
                                 + klocal + (l >> 4) * 8) * 2;
                    uint32_t fa[4], fl[4];
                    ldsm_x4(fa, ah);
                    ldsm_x4(fl, ah + HBYTES);
#pragma unroll
                    for (int g = 0; g < 2; g++) {
                        const uint32_t* wr = wreg[r*4+j][g][0];
                        const uint32_t* wl = wreg[r*4+j][g][1];
                        mma16816(acc[mt][g], fa, wr[0], wr[1]);
                        mma16816(acc[mt][g], fa, wl[0], wl[1]);
                        mma16816(acc[mt][g], fl, wr[0], wr[1]);
                    }
                }
            }
            __syncthreads();
        }

        {
            float* my = red + (size_t)tid * 32;
#pragma unroll
            for (int mt = 0; mt < 4; mt++)
#pragma unroll
                for (int g = 0; g < 2; g++)
#pragma unroll
                    for (int e = 0; e < 4; e++)
                        my[(mt*2 + g)*4 + e] = acc[mt][g][e];
        }
        __syncthreads();
        {
            int lr = tid >> 3, r0 = (tid & 7) * 4;
            float4 s = make_float4(0.f, 0.f, 0.f, 0.f);
#pragma unroll
            for (int ww = 0; ww < 8; ww++) {
                float4 p = *(const float4*)(red + (size_t)(ww*32 + lr)*32 + r0);
                s.x += p.x; s.y += p.y; s.z += p.z; s.w += p.w;
            }
            *(float4*)(fin + lr*32 + r0) = s;
        }
        __syncthreads();

#pragma unroll
        for (int i = 0; i < 2; i++) {
            int row = prow[i], nl = pnl[i], n = n0 + nl;
            int mt = row >> 4, r4 = row & 15;
            int ll = (r4 & 7) * 4 + (nl >> 1);
            int e  = ((r4 >> 3) << 1) + (nl & 1);
            float ar = fin[ll*32 + (mt*2 + 0)*4 + e];
            float a1 = fin[ll*32 + (mt*2 + 1)*4 + e];
            size_t mtn = ((size_t)row * SS + t) * HH + n;
            float rg = 1.f / (1.f + expf(-(ar + xr[i])));
            float zg = 1.f / (1.f + expf(-(xtz[mtn] + xz[i])));
            float t1 = tanhf(xth1[mtn] + rg * (a1 + b1c[i]));
            float ht = (1.f - zg) * t1 + zg * hp[i];
            hp[i] = ht;
            hts[mtn] = ht;
            __nv_bfloat16 hb = __float2bfloat16(ht);
            __nv_bfloat16 lb = __float2bfloat16(ht - __bfloat162float(hb));
            hs_h[(size_t)slot_out * BB * HH + (size_t)row * HH + n] = hb;
            hs_l[(size_t)slot_out * BB * HH + (size_t)row * HH + n] = lb;
        }

        __threadfence();
        __syncthreads();
        if (tid == 0) {
            atomicAdd(&g_bar, 1);
            const int target = 128 * (t + 1);
            while (*(volatile int*)&g_bar < target) { }
        }
        __syncthreads();
    }

    if (tid == 0) atomicAdd(&g_ack, 1);
    if (blockIdx.x == 0 && tid == 0) {
        while (*(volatile int*)&g_ack < 128) { }
        g_bar = 0;
        g_ack = 0;
        __threadfence();
    }
}

// ======================= host launcher =======================
extern "C" void kernel_launch(void* const* d_in, const int* in_sizes, int n_in,
                              void* d_out, int out_size)
{
    const float* x     = (const float*)d_in[0];
    const float* h0    = (const float*)d_in[1];
    const float* Wxe   = (const float*)d_in[2];
    const float* bxe   = (const float*)d_in[3];
    const float* Wep   = (const float*)d_in[4];
    const float* bep   = (const float*)d_in[5];
    const float* Whr   = (const float*)d_in[6];
    const float* bhr   = (const float*)d_in[7];
    const float* Wx0r  = (const float*)d_in[8];
    const float* bx0r  = (const float*)d_in[9];
    const float* Wxtz  = (const float*)d_in[10];
    const float* bxtz  = (const float*)d_in[11];
    const float* Wx0z  = (const float*)d_in[12];
    const float* bx0z  = (const float*)d_in[13];
    const float* Wxth1 = (const float*)d_in[14];
    const float* bxth1 = (const float*)d_in[15];
    const float* Wh1h1 = (const float*)d_in[16];
    const float* bh1h1 = (const float*)d_in[17];

    float* out  = (float*)d_out;
    float* hts  = out;
    float* ptes = hts  + (size_t)BB*SS*HH;
    float* p0es = ptes + (size_t)BB*SS*CC;
    float* xtes = p0es + (size_t)BB*SS*CC;
    float* x0es = xtes + (size_t)BB*SS*HH;

    float *p_xtz, *p_xth1, *p_x0r, *p_x0z;
    __nv_bfloat16 *x_h, *x_l, *wxe_h, *wxe_l, *e_h, *e_l, *wz_h, *wz_l, *wh_h, *wh_l;
    __nv_bfloat16 *hs_h, *hs_l;
    cudaGetSymbolAddress((void**)&p_xtz,  g_xtz);
    cudaGetSymbolAddress((void**)&p_xth1, g_xth1);
    cudaGetSymbolAddress((void**)&p_x0r,  g_x0r);
    cudaGetSymbolAddress((void**)&p_x0z,  g_x0z);
    cudaGetSymbolAddress((void**)&x_h,    g_x_h);
    cudaGetSymbolAddress((void**)&x_l,    g_x_l);
    cudaGetSymbolAddress((void**)&wxe_h,  g_wxe_h);
    cudaGetSymbolAddress((void**)&wxe_l,  g_wxe_l);
    cudaGetSymbolAddress((void**)&e_h,    g_e_h);
    cudaGetSymbolAddress((void**)&e_l,    g_e_l);
    cudaGetSymbolAddress((void**)&wz_h,   g_wz_h);
    cudaGetSymbolAddress((void**)&wz_l,   g_wz_l);
    cudaGetSymbolAddress((void**)&wh_h,   g_wh_h);
    cudaGetSymbolAddress((void**)&wh_l,   g_wh_l);
    cudaGetSymbolAddress((void**)&hs_h,   g_hs_h);
    cudaGetSymbolAddress((void**)&hs_l,   g_hs_l);

    cudaFuncSetAttribute(hmma_gemm, cudaFuncAttributeMaxDynamicSharedMemorySize, 2 * STG_B);
    cudaFuncSetAttribute(rec_hmma,  cudaFuncAttributeMaxDynamicSharedMemorySize, RSMEM_H);

    // launch order: gemm1 at index 3 (profiled slot)
    pack_rm<<<(MM*FF/4 + 255)/256, 256>>>(x, x_h, x_l, MM*FF);                 // 0
    pack_tr<<<dim3(HH/32, FF/32), 256>>>(Wxe, wxe_h, wxe_l, FF, HH);           // 1
    pack_h0<<<(BB*HH/4 + 255)/256, 256>>>(h0, hs_h + (size_t)BB*HH,            // 2
                                          hs_l + (size_t)BB*HH);
    hmma_gemm<<<dim3(HH/128, MM/128), 256, 2*STG_B>>>(                         // 3
        x_h, x_l, wxe_h, wxe_l, bxe, xtes, MM, HH, FF, 1, e_h, e_l, x0es,
        (__nv_bfloat16*)0, (__nv_bfloat16*)0, (float*)0, (float*)0);

    pack_tr<<<dim3(HH/32, HH/32), 256>>>(Wxtz,  wz_h, wz_l, HH, HH);           // 4
    pack_tr<<<dim3(HH/32, HH/32), 256>>>(Wxth1, wh_h, wh_l, HH, HH);           // 5
    ptes_kernel<<<MM/8, 256>>>(xtes, Wep, bep, ptes);                          // 6
    bcast_p0es<<<(BB*SS*CC + 255)/256, 256>>>(ptes, p0es);                     // 7

    // merged gemm2+gemm3: one launch, dual-N
    hmma_gemm<<<dim3(2*HH/128, MM/128), 256, 2*STG_B>>>(                       // 8
        e_h, e_l, wz_h, wz_l, bxtz, p_xtz, MM, HH, HH, 0,
        (__nv_bfloat16*)0, (__nv_bfloat16*)0, (float*)0,
        wh_h, wh_l, bxth1, p_xth1);

    dual64_kernel<<<HH/16, 256>>>(xtes + (size_t)(SS-1)*HH, SS*HH,             // 9
                                  Wx0r, Wx0z, bx0r, bx0z, p_x0r, p_x0z);

    rec_hmma<<<128, 256, RSMEM_H>>>(h0, Whr, Wh1h1, bhr, bh1h1,                // 10
                                    p_x0r, p_x0z, p_xtz, p_xth1,
                                    hts, hs_h, hs_l);
}